// round 8
// baseline (speedup 1.0000x reference)
#include <cuda_runtime.h>
#include <math_constants.h>

#define N_POINTS 50000
#define CHANNELS 64
#define CAP 128           // bucket capacity per point; counts ~Poisson(32), max ~66
#define OVF_CAP (1 << 20) // overflow list capacity (expected usage: 0)

// Static scratch (no allocations). __device__ globals are zero-initialized at
// module load; segmax_kernel restores all counters to zero after consuming
// them, so the zero-invariant holds for every call and graph replay.
__device__ int d_cursor[N_POINTS];
__device__ int d_bucket[N_POINTS * CAP];   // 25.6 MB, 512B-aligned rows
__device__ int d_ovf_count;
__device__ int d_ovf_list[OVF_CAP];        // edge ids that exceeded CAP
__device__ int d_done;                     // K3 block-arrival counter

// ---------------------------------------------------------------------------
// K2: bucket-build. FOUR edges per thread (two int4 index loads) -> 4
// independent atomicAdd->store chains in flight per thread. 1.6M atomics.
// Edges whose bucket is full go to the overflow list (folded into K3).
// ---------------------------------------------------------------------------
__device__ __forceinline__ void bucket_one(int e, int o_idx, int i_idx) {
    int pos = atomicAdd(&d_cursor[o_idx], 1);
    if (pos < CAP) {
        d_bucket[o_idx * CAP + pos] = i_idx;
    } else {
        int op = atomicAdd(&d_ovf_count, 1);
        if (op < OVF_CAP) d_ovf_list[op] = e;
    }
}

__global__ void bucket_kernel(const int* __restrict__ idx, int n_edges) {
    int t = blockIdx.x * blockDim.x + threadIdx.x;
    int e0 = t * 4;
    if (e0 + 4 <= n_edges) {
        int4 a = __ldg(reinterpret_cast<const int4*>(idx) + 2 * t);
        int4 b = __ldg(reinterpret_cast<const int4*>(idx) + 2 * t + 1);
        bucket_one(e0,     a.x, a.y);
        bucket_one(e0 + 1, a.z, a.w);
        bucket_one(e0 + 2, b.x, b.y);
        bucket_one(e0 + 3, b.z, b.w);
    } else {
        for (int e = e0; e < n_edges; e++) {
            int2 pr = __ldg(reinterpret_cast<const int2*>(idx) + e);
            bucket_one(e, pr.x, pr.y);
        }
    }
}

// ---------------------------------------------------------------------------
// K3: dense segment-max, software-pipelined. 16 lanes per point, one float4
// (4 channels) per lane. The next iteration's int4 of bucket indices is
// prefetched while the current 4 feature-row gathers are in flight, halving
// the exposed latency per iteration. All addressing is 32-bit.
// Write-only store (covers empty segments -> -inf). Overflow edges
// (expected: none) folded in via a guarded scan of the compact list.
// Self-clean epilogue restores zeroed counters (replaces an init kernel).
// ---------------------------------------------------------------------------
__device__ __forceinline__ float4 max4(float4 a, float4 b) {
    return make_float4(fmaxf(a.x, b.x), fmaxf(a.y, b.y),
                       fmaxf(a.z, b.z), fmaxf(a.w, b.w));
}

// Exact grid: N_POINTS*16 threads, 256/block -> no early exits; __syncthreads
// in the epilogue is safe.
static_assert((N_POINTS * 16) % 256 == 0, "grid must be exact");

__global__ void __launch_bounds__(256)
segmax_kernel(const float* __restrict__ feat,
              const int* __restrict__ idx,
              float* __restrict__ out) {
    int t = blockIdx.x * blockDim.x + threadIdx.x;
    int p = t >> 4;
    int c4 = (t & 15) << 2;

    int cnt = d_cursor[p];
    if (cnt > CAP) cnt = CAP;
    const int* bkt = d_bucket + p * CAP;         // 512B-aligned
    const float* featc = feat + c4;              // per-lane channel base

    float4 acc = make_float4(-CUDART_INF_F, -CUDART_INF_F, -CUDART_INF_F, -CUDART_INF_F);

    int i = 0;
    if (cnt >= 4) {
        // Prime: first index quad.
        int4 s = __ldg(reinterpret_cast<const int4*>(bkt));
        // Pipelined main loop: prefetch quad i+4 while gathering quad i.
        for (; i + 8 <= cnt; i += 4) {
            int4 sn = __ldg(reinterpret_cast<const int4*>(bkt + i + 4));
            float4 v0 = __ldg(reinterpret_cast<const float4*>(featc + s.x * CHANNELS));
            float4 v1 = __ldg(reinterpret_cast<const float4*>(featc + s.y * CHANNELS));
            float4 v2 = __ldg(reinterpret_cast<const float4*>(featc + s.z * CHANNELS));
            float4 v3 = __ldg(reinterpret_cast<const float4*>(featc + s.w * CHANNELS));
            acc = max4(acc, max4(max4(v0, v1), max4(v2, v3)));
            s = sn;
        }
        // Drain the primed quad.
        {
            float4 v0 = __ldg(reinterpret_cast<const float4*>(featc + s.x * CHANNELS));
            float4 v1 = __ldg(reinterpret_cast<const float4*>(featc + s.y * CHANNELS));
            float4 v2 = __ldg(reinterpret_cast<const float4*>(featc + s.z * CHANNELS));
            float4 v3 = __ldg(reinterpret_cast<const float4*>(featc + s.w * CHANNELS));
            acc = max4(acc, max4(max4(v0, v1), max4(v2, v3)));
            i += 4;
        }
    }
    #pragma unroll 1
    for (; i < cnt; i++) {
        int s = __ldg(bkt + i);
        float4 v = __ldg(reinterpret_cast<const float4*>(featc + s * CHANNELS));
        acc = max4(acc, v);
    }

    // Exactness guard: fold in any overflow edges targeting this point.
    // One L2-hot broadcast load; branch ~never taken.
    int ovf = d_ovf_count;
    if (ovf > 0) {
        if (ovf > OVF_CAP) ovf = OVF_CAP;
        #pragma unroll 1
        for (int j = 0; j < ovf; j++) {
            int e = d_ovf_list[j];
            int2 pr = __ldg(reinterpret_cast<const int2*>(idx) + e);
            if (pr.x == p) {
                float4 v = __ldg(reinterpret_cast<const float4*>(featc + pr.y * CHANNELS));
                acc = max4(acc, v);
            }
        }
    }

    *reinterpret_cast<float4*>(out + p * CHANNELS + c4) = acc;

    // --- Self-clean epilogue (replaces an init kernel) ---
    __syncthreads();                       // everyone in block done reading
    if ((t & 15) == 0) d_cursor[p] = 0;    // one lane per point
    if (threadIdx.x == 0) {
        __threadfence();
        int old = atomicAdd(&d_done, 1);
        if (old == gridDim.x - 1) {        // last block: all reads of
            d_ovf_count = 0;               // d_ovf_count already happened
            d_done = 0;
        }
    }
}

extern "C" void kernel_launch(void* const* d_in, const int* in_sizes, int n_in,
                              void* d_out, int out_size) {
    const float* feat = (const float*)d_in[0];   // [N_POINTS, 64] f32
    const int* idx = (const int*)d_in[1];        // [N_EDGES, 2] i32
    float* out = (float*)d_out;                  // [N_POINTS, 64] f32

    int n_edges = in_sizes[1] / 2;

    // K2: bucket build (4 edges / thread)
    int nt4 = (n_edges + 3) / 4;
    bucket_kernel<<<(nt4 + 255) / 256, 256>>>(idx, n_edges);

    // K3: dense per-point max (16 lanes/point), pipelined, + self-clean
    segmax_kernel<<<(N_POINTS * 16) / 256, 256>>>(feat, idx, out);
}